// round 16
// baseline (speedup 1.0000x reference)
#include <cuda_runtime.h>
#include <cuda_bf16.h>
#include <math.h>
#include <stdint.h>

// Problem constants
#define BB   2
#define TT   2048
#define CC   2048
#define NHH  16
#define DKK  128
#define LATT 512
#define DHRR 64
#define MROWS (BB * TT)   // 4096

typedef __nv_bfloat16 bf16;

// ---------------------------------------------------------------------------
// Scratch (static device globals -- no allocation allowed)
// ---------------------------------------------------------------------------
__device__ float g_h   [(size_t)MROWS * 1024];
__device__ float g_kr  [(size_t)MROWS * 64];
__device__ float g_qr  [(size_t)MROWS * 1024];

__device__ bf16 g_xhi [(size_t)MROWS * 2048];
__device__ bf16 g_xlo [(size_t)MROWS * 2048];
__device__ bf16 g_hhi [(size_t)MROWS * 1024];
__device__ bf16 g_hlo [(size_t)MROWS * 1024];
__device__ bf16 g_athi[(size_t)MROWS * 2048];
__device__ bf16 g_atlo[(size_t)MROWS * 2048];

__device__ bf16 g_wdkvh[(size_t)1024 * 2048];
__device__ bf16 g_wdkvl[(size_t)1024 * 2048];
__device__ bf16 g_wqrh [(size_t)1024 * 1024];
__device__ bf16 g_wqrl [(size_t)1024 * 1024];
__device__ bf16 g_wuvh [(size_t)4096 * 512];
__device__ bf16 g_wuvl [(size_t)4096 * 512];
__device__ bf16 g_wuqh [(size_t)2048 * 512];
__device__ bf16 g_wuql [(size_t)2048 * 512];
__device__ bf16 g_woh  [(size_t)2048 * 2048];
__device__ bf16 g_wol  [(size_t)2048 * 2048];

__device__ bf16 g_qhi[(size_t)BB * NHH * TT * 192];
__device__ bf16 g_qlo[(size_t)BB * NHH * TT * 192];
__device__ bf16 g_khi[(size_t)BB * NHH * TT * 192];
__device__ bf16 g_klo[(size_t)BB * NHH * TT * 192];
__device__ bf16 g_vhi[(size_t)BB * NHH * TT * 128];
__device__ bf16 g_vlo[(size_t)BB * NHH * TT * 128];

#define SCLQ 0.12754984837627695f   // 1/sqrt(128) * log2(e)

// ---------------------------------------------------------------------------
// PTX helpers
// ---------------------------------------------------------------------------
__device__ __forceinline__ uint32_t smem_u32(const void* p)
{ return (uint32_t)__cvta_generic_to_shared(p); }

__device__ __forceinline__ void cp16(uint32_t dst, const void* src)
{ asm volatile("cp.async.cg.shared.global [%0], [%1], 16;\n" :: "r"(dst), "l"(src)); }

__device__ __forceinline__ void cp_commit()
{ asm volatile("cp.async.commit_group;\n"); }

template <int N>
__device__ __forceinline__ void cp_wait()
{ asm volatile("cp.async.wait_group %0;\n" :: "n"(N)); }

__device__ __forceinline__ void ldm_x4(uint32_t* r, uint32_t addr)
{
    asm volatile("ldmatrix.sync.aligned.m8n8.x4.shared.b16 {%0,%1,%2,%3}, [%4];\n"
        : "=r"(r[0]), "=r"(r[1]), "=r"(r[2]), "=r"(r[3]) : "r"(addr));
}
__device__ __forceinline__ void ldm_x4t(uint32_t* r, uint32_t addr)
{
    asm volatile("ldmatrix.sync.aligned.m8n8.x4.trans.shared.b16 {%0,%1,%2,%3}, [%4];\n"
        : "=r"(r[0]), "=r"(r[1]), "=r"(r[2]), "=r"(r[3]) : "r"(addr));
}
__device__ __forceinline__ void mma_bf16(float* d, const uint32_t* a, const uint32_t* b)
{
    asm volatile(
        "mma.sync.aligned.m16n8k16.row.col.f32.bf16.bf16.f32 "
        "{%0,%1,%2,%3}, {%4,%5,%6,%7}, {%8,%9}, {%0,%1,%2,%3};\n"
        : "+f"(d[0]), "+f"(d[1]), "+f"(d[2]), "+f"(d[3])
        : "r"(a[0]), "r"(a[1]), "r"(a[2]), "r"(a[3]), "r"(b[0]), "r"(b[1]));
}
__device__ __forceinline__ float ex2f(float x)
{ float y; asm("ex2.approx.f32 %0, %1;" : "=f"(y) : "f"(x)); return y; }

__device__ __forceinline__ uint32_t packbf2(float lo, float hi)
{ uint32_t d; asm("cvt.rn.bf16x2.f32 %0, %1, %2;" : "=r"(d) : "f"(hi), "f"(lo)); return d; }

__device__ __forceinline__ float bfround(float v)
{ return __bfloat162float(__float2bfloat16(v)); }

// ---------------------------------------------------------------------------
// prep_a: x split + W_dkv transpose (only what the h-GEMM needs)
// blocks [0,8192): x split; [8192,10240): W_dkv tiles
// ---------------------------------------------------------------------------
__global__ __launch_bounds__(256)
void prep_a(const float* __restrict__ x, const float* __restrict__ Wdkv,
            bf16* __restrict__ xhi, bf16* __restrict__ xlo,
            bf16* __restrict__ wdkvh, bf16* __restrict__ wdkvl)
{
    __shared__ float ts[32][33];
    const int bid = blockIdx.x, tid = threadIdx.x;

    if (bid < 8192) {
        int idx = bid * 256 + tid;
        int m = idx >> 9, k4 = (idx & 511) * 4;
        float4 v = *(const float4*)&x[(size_t)m * 2048 + k4];
        float h0 = bfround(v.x), h1 = bfround(v.y);
        float h2 = bfround(v.z), h3 = bfround(v.w);
        uint2 ph, pl;
        ph.x = packbf2(h0, h1); ph.y = packbf2(h2, h3);
        pl.x = packbf2(v.x - h0, v.y - h1); pl.y = packbf2(v.z - h2, v.w - h3);
        *(uint2*)&xhi[(size_t)m * 2048 + k4] = ph;
        *(uint2*)&xlo[(size_t)m * 2048 + k4] = pl;
        return;
    }

    // W_dkv: K=2048, N=1024
    int tl = bid - 8192;
    int n0 = (tl % 32) * 32, k0 = (tl / 32) * 32;
    int tx = tid & 31, ty = tid >> 5;
#pragma unroll
    for (int r = 0; r < 4; r++)
        ts[ty + 8 * r][tx] = Wdkv[(size_t)(k0 + ty + 8 * r) * 1024 + n0 + tx];
    __syncthreads();
#pragma unroll
    for (int r = 0; r < 4; r++) {
        float v = ts[tx][ty + 8 * r];
        bf16 h = __float2bfloat16(v);
        size_t o = (size_t)(n0 + ty + 8 * r) * 2048 + k0 + tx;
        wdkvh[o] = h;
        wdkvl[o] = __float2bfloat16(v - __bfloat162float(h));
    }
}

// ---------------------------------------------------------------------------
// Fused rope + hi/lo split + per-head scatter (qr blocks then kr blocks)
// ---------------------------------------------------------------------------
__global__ void rope_split_both(const float* __restrict__ qr,
                                const float* __restrict__ kr,
                                bf16* __restrict__ qhi, bf16* __restrict__ qlo,
                                bf16* __restrict__ khi, bf16* __restrict__ klo)
{
    const int bid = blockIdx.x, tid = threadIdx.x;
    if (bid < 8192) {
        int idx = bid * 256 + tid;
        int row = idx >> 9, i = idx & 511;
        int t = row & 2047, b = row >> 11;
        float theta = (float)exp(-2.0 * (double)i / 1024.0 * log(10000.0));
        float angle = (float)(t + 1) * theta;
        double a = (double)angle;
        float cs = (float)cos(a), sn = (float)sin(a);
        const float* p = qr + (size_t)row * 1024 + 2 * i;
        float x0 = p[0], x1 = p[1];
        float p0 = (x0 * cs - x1 * sn) * SCLQ;
        float p1 = (x1 * cs + x0 * sn) * SCLQ;
        int h = (2 * i) >> 6, d = (2 * i) & 63;
        size_t base = ((size_t)((b * NHH + h) * TT) + t) * 192 + 128 + d;
        float f0 = bfround(p0), f1 = bfround(p1);
        *(uint32_t*)&qhi[base] = packbf2(f0, f1);
        *(uint32_t*)&qlo[base] = packbf2(p0 - f0, p1 - f1);
    } else {
        int idx = (bid - 8192) * 256 + tid;
        int row = idx >> 5, i = idx & 31;
        int t = row & 2047, b = row >> 11;
        float theta = (float)exp(-2.0 * (double)i / 64.0 * log(10000.0));
        float angle = (float)(t + 1) * theta;
        double a = (double)angle;
        float cs = (float)cos(a), sn = (float)sin(a);
        const float* p = kr + (size_t)row * 64 + 2 * i;
        float x0 = p[0], x1 = p[1];
        float p0 = x0 * cs - x1 * sn;
        float p1 = x1 * cs + x0 * sn;
        float f0 = bfround(p0), f1 = bfround(p1);
        uint32_t ph = packbf2(f0, f1), pl = packbf2(p0 - f0, p1 - f1);
#pragma unroll
        for (int hh = 0; hh < NHH; hh++) {
            size_t base = ((size_t)((b * NHH + hh) * TT) + t) * 192 + 128 + 2 * i;
            *(uint32_t*)&khi[base] = ph;
            *(uint32_t*)&klo[base] = pl;
        }
    }
}

// ---------------------------------------------------------------------------
// Shared HMMA GEMM body (compensated hi/lo, fused epilogues) — R12 proven.
// ---------------------------------------------------------------------------
#define TST 40
#define A_ELE (128 * TST)
#define B_ELE (128 * TST)
#define STG_ELE (2 * A_ELE + 2 * B_ELE)
#define GSMEM (2 * STG_ELE * 2)

__device__ __forceinline__
void gemm_body(int brow, int bcol,
               const bf16* __restrict__ Ahi, const bf16* __restrict__ Alo,
               int lda, int aoff,
               const bf16* __restrict__ Bhi, const bf16* __restrict__ Blo,
               int ldb,
               const float* __restrict__ bias,
               float* __restrict__ Y, int ldy, int K,
               bf16* __restrict__ ho, bf16* __restrict__ lo_,
               bf16* __restrict__ ho2, bf16* __restrict__ lo2, int mode,
               bf16* dsm)
{
    const uint32_t sb0 = smem_u32(dsm);
    const int tid = threadIdx.x, lane = tid & 31, wid = tid >> 5;
    const int wm = (wid >> 1) * 64, wn = (wid & 1) * 64;

    auto issue = [&](int st, int kt) {
        uint32_t s = sb0 + (uint32_t)(st * STG_ELE) * 2;
        int ke = kt * 32;
#pragma unroll
        for (int i = 0; i < 4; i++) {
            int c = tid + i * 128;
            int r = c >> 2, sg = (c & 3) * 8;
            uint32_t d = (uint32_t)(r * TST + sg) * 2;
            cp16(s + d, Ahi + (size_t)(brow + r) * lda + aoff + ke + sg);
            cp16(s + (uint32_t)A_ELE * 2 + d,
                 Alo + (size_t)(brow + r) * lda + aoff + ke + sg);
            cp16(s + (uint32_t)(2 * A_ELE) * 2 + d,
                 Bhi + (size_t)(bcol + r) * ldb + ke + sg);
            cp16(s + (uint32_t)(2 * A_ELE + B_ELE) * 2 + d,
                 Blo + (size_t)(bcol + r) * ldb + ke + sg);
        }
        cp_commit();
    };

    float acc[4][8][4];
#pragma unroll
    for (int i = 0; i < 4; i++)
#pragma unroll
        for (int j = 0; j < 8; j++)
#pragma unroll
            for (int f = 0; f < 4; f++) acc[i][j][f] = 0.f;

    const int ntiles = K / 32;
    issue(0, 0);
    issue(1, 1);

    const int l16 = lane & 15, lhi = (lane >> 4) * 8;
    const int brofs = (lane & 7) + ((lane >> 4) & 1) * 8;
    const int bcofs = ((lane >> 3) & 1) * 8;

    for (int kt = 0; kt < ntiles; kt++) {
        if (kt + 1 < ntiles) { cp_wait<1>(); } else { cp_wait<0>(); }
        __syncthreads();
        int cur = kt & 1;
        uint32_t s = sb0 + (uint32_t)(cur * STG_ELE) * 2;
        uint32_t sAh = s, sAl = s + (uint32_t)A_ELE * 2;
        uint32_t sBh = s + (uint32_t)(2 * A_ELE) * 2;
        uint32_t sBl = sBh + (uint32_t)B_ELE * 2;

#pragma unroll
        for (int kk = 0; kk < 32; kk += 16) {
            uint32_t bh[4][4], bl[4][4];
#pragma unroll
            for (int j2 = 0; j2 < 4; j2++) {
                uint32_t baddr =
                    (uint32_t)((wn + j2 * 16 + brofs) * TST + kk + bcofs) * 2;
                ldm_x4(bh[j2], sBh + baddr);
                ldm_x4(bl[j2], sBl + baddr);
            }
#pragma unroll
            for (int i = 0; i < 4; i++) {
                uint32_t ah[4], al[4];
                uint32_t aaddr = (uint32_t)((wm + i * 16 + l16) * TST + kk + lhi) * 2;
                ldm_x4(ah, sAh + aaddr);
                ldm_x4(al, sAl + aaddr);
#pragma unroll
                for (int j2 = 0; j2 < 4; j2++) {
                    mma_bf16(acc[i][2 * j2],     ah, bh[j2]);
                    mma_bf16(acc[i][2 * j2 + 1], ah, bh[j2] + 2);
                }
#pragma unroll
                for (int j2 = 0; j2 < 4; j2++) {
                    mma_bf16(acc[i][2 * j2],     ah, bl[j2]);
                    mma_bf16(acc[i][2 * j2 + 1], ah, bl[j2] + 2);
                }
#pragma unroll
                for (int j2 = 0; j2 < 4; j2++) {
                    mma_bf16(acc[i][2 * j2],     al, bh[j2]);
                    mma_bf16(acc[i][2 * j2 + 1], al, bh[j2] + 2);
                }
            }
        }
        __syncthreads();
        if (kt + 2 < ntiles) issue(cur, kt + 2);
    }

#pragma unroll
    for (int i = 0; i < 4; i++) {
#pragma unroll
        for (int j = 0; j < 8; j++) {
            int r0 = brow + wm + i * 16 + (lane >> 2);
            int c0 = bcol + wn + j * 8 + (lane & 3) * 2;
            float b0 = bias[c0], b1 = bias[c0 + 1];
            float v00 = acc[i][j][0] + b0, v01 = acc[i][j][1] + b1;
            float v10 = acc[i][j][2] + b0, v11 = acc[i][j][3] + b1;

            if (mode <= 1) {
                *(float2*)&Y[(size_t)r0 * ldy + c0]       = make_float2(v00, v01);
                *(float2*)&Y[(size_t)(r0 + 8) * ldy + c0] = make_float2(v10, v11);
            }
            if (mode == 1) {
                float f00 = bfround(v00), f01 = bfround(v01);
                float f10 = bfround(v10), f11 = bfround(v11);
                *(uint32_t*)&ho [(size_t)r0 * ldy + c0]       = packbf2(f00, f01);
                *(uint32_t*)&lo_[(size_t)r0 * ldy + c0]       = packbf2(v00 - f00, v01 - f01);
                *(uint32_t*)&ho [(size_t)(r0 + 8) * ldy + c0] = packbf2(f10, f11);
                *(uint32_t*)&lo_[(size_t)(r0 + 8) * ldy + c0] = packbf2(v10 - f10, v11 - f11);
            } else if (mode == 2) {
#pragma unroll
                for (int rr = 0; rr < 2; rr++) {
                    int r = r0 + rr * 8;
                    float va = rr ? v10 : v00, vb = rr ? v11 : v01;
                    int b = r >> 11, t = r & 2047;
                    float fa = bfround(va), fb = bfround(vb);
                    if (c0 < 2048) {
                        int hh = c0 >> 7, d = c0 & 127;
                        size_t base = ((size_t)(b * NHH + hh) * TT + t) * 192 + d;
                        *(uint32_t*)&ho [base] = packbf2(fa, fb);
                        *(uint32_t*)&lo_[base] = packbf2(va - fa, vb - fb);
                    } else {
                        int c2 = c0 - 2048;
                        int hh = c2 >> 7, d = c2 & 127;
                        size_t base = ((size_t)(b * NHH + hh) * TT + t) * 128 + d;
                        *(uint32_t*)&ho2[base] = packbf2(fa, fb);
                        *(uint32_t*)&lo2[base] = packbf2(va - fa, vb - fb);
                    }
                }
            } else if (mode == 3) {
#pragma unroll
                for (int rr = 0; rr < 2; rr++) {
                    int r = r0 + rr * 8;
                    float va = (rr ? v10 : v00) * SCLQ, vb = (rr ? v11 : v01) * SCLQ;
                    int b = r >> 11, t = r & 2047;
                    int hh = c0 >> 7, d = c0 & 127;
                    size_t base = ((size_t)(b * NHH + hh) * TT + t) * 192 + d;
                    float fa = bfround(va), fb = bfround(vb);
                    *(uint32_t*)&ho [base] = packbf2(fa, fb);
                    *(uint32_t*)&lo_[base] = packbf2(va - fa, vb - fb);
                }
            }
        }
    }
}

// Standalone GEMM (out projection)
__global__ __launch_bounds__(128, 2)
void gemm_mma(const bf16* __restrict__ Ahi, const bf16* __restrict__ Alo,
              int lda, int aoff,
              const bf16* __restrict__ Bhi, const bf16* __restrict__ Blo,
              int ldb,
              const float* __restrict__ bias,
              float* __restrict__ Y, int ldy, int K,
              bf16* __restrict__ ho, bf16* __restrict__ lo_,
              bf16* __restrict__ ho2, bf16* __restrict__ lo2, int mode)
{
    extern __shared__ bf16 dsm[];
    gemm_body(blockIdx.y * 128, blockIdx.x * 128, Ahi, Alo, lda, aoff,
              Bhi, Blo, ldb, bias, Y, ldy, K, ho, lo_, ho2, lo2, mode, dsm);
}

// h-GEMM + overlapped weight conversions.
// Blocks [0,256): h GEMM (mode 1). Blocks [256,320): persistent converters
// grid-striding over 8192 32x32 transpose tiles of W_o/W_qr/W_uv/W_uq.
__global__ __launch_bounds__(128, 2)
void gemm_h_fused(const bf16* __restrict__ xhi, const bf16* __restrict__ xlo,
                  const bf16* __restrict__ wdkvh, const bf16* __restrict__ wdkvl,
                  const float* __restrict__ b_dkv, float* __restrict__ h,
                  bf16* __restrict__ hhi, bf16* __restrict__ hlo,
                  const float* __restrict__ Wo,  const float* __restrict__ Wqr,
                  const float* __restrict__ Wuv, const float* __restrict__ Wuq,
                  bf16* __restrict__ woh,  bf16* __restrict__ wol,
                  bf16* __restrict__ wqrh, bf16* __restrict__ wqrl,
                  bf16* __restrict__ wuvh, bf16* __restrict__ wuvl,
                  bf16* __restrict__ wuqh, bf16* __restrict__ wuql)
{
    extern __shared__ bf16 dsm[];
    const int id = blockIdx.x;
    if (id < 256) {
        int bx = id & 7, by = id >> 3;
        gemm_body(by * 128, bx * 128, xhi, xlo, 2048, 0, wdkvh, wdkvl, 2048,
                  b_dkv, h, 1024, 2048, hhi, hlo, 0, 0, 1, dsm);
        return;
    }

    // converter: 64 blocks, 128 threads, tiles (id-256) + 64*i
    float* ts = (float*)dsm;            // [32][33]
    const int tid = threadIdx.x;
    const int tx = tid & 31, ty = tid >> 5;  // ty in 0..3
    for (int tt = id - 256; tt < 8192; tt += 64) {
        const float* W; bf16 *hiT, *loT; int K, N, tl;
        if (tt < 4096)      { W = Wo;  hiT = woh;  loT = wol;  K = 2048; N = 2048; tl = tt; }
        else if (tt < 5120) { W = Wqr; hiT = wqrh; loT = wqrl; K = 1024; N = 1024; tl = tt - 4096; }
        else if (tt < 7168) { W = Wuv; hiT = wuvh; loT = wuvl; K = 512;  N = 4096; tl = tt - 5120; }
        else                { W = Wuq; hiT = wuqh; loT = wuql; K = 512;  N = 2048; tl = tt - 7168; }
        int ntx = N / 32;
        int n0 = (tl % ntx) * 32, k0 = (tl / ntx) * 32;
        __syncthreads();
#pragma unroll
        for (int r = 0; r < 8; r++)
            ts[(ty + 4 * r) * 33 + tx] = W[(size_t)(k0 + ty + 4 * r) * N + n0 + tx];
        __syncthreads();
#pragma unroll
        for (int r = 0; r < 8; r++) {
            float v = ts[tx * 33 + ty + 4 * r];
            bf16 hh = __float2bfloat16(v);
            size_t o = (size_t)(n0 + ty + 4 * r) * K + k0 + tx;
            hiT[o] = hh;
            loT[o] = __float2bfloat16(v - __bfloat162float(hh));
        }
    }
}

// Fused qr + kv + q GEMMs + kr mini-GEMM; one launch, range dispatch.
__global__ __launch_bounds__(128, 2)
void gemm_fused3(const bf16* __restrict__ hhi, const bf16* __restrict__ hlo,
                 const bf16* __restrict__ wqrh, const bf16* __restrict__ wqrl,
                 const float* __restrict__ b_qr, float* __restrict__ qr,
                 const bf16* __restrict__ wuvh, const bf16* __restrict__ wuvl,
                 const float* __restrict__ b_uv,
                 bf16* __restrict__ khi, bf16* __restrict__ klo,
                 bf16* __restrict__ vhi, bf16* __restrict__ vlo,
                 const bf16* __restrict__ wuqh, const bf16* __restrict__ wuql,
                 const float* __restrict__ b_uq,
                 bf16* __restrict__ qhi, bf16* __restrict__ qlo,
                 const float* __restrict__ h, const float* __restrict__ W_kr,
                 const float* __restrict__ b_kr, float* __restrict__ kr)
{
    extern __shared__ bf16 dsm[];
    const int id = blockIdx.x;
    if (id < 256) {
        int bx = id & 7, by = id >> 3;
        gemm_body(by * 128, bx * 128, hhi, hlo, 1024, 0, wqrh, wqrl, 1024,
                  b_qr, qr, 1024, 1024, 0, 0, 0, 0, 0, dsm);
    } else if (id < 1280) {
        int t = id - 256;
        int bx = t & 31, by = t >> 5;
        gemm_body(by * 128, bx * 128, hhi, hlo, 1024, 0, wuvh, wuvl, 512,
                  b_uv, 0, 512, 512, khi, klo, vhi, vlo, 2, dsm);
    } else if (id < 1792) {
        int t = id - 1280;
        int bx = t & 15, by = t >> 4;
        gemm_body(by * 128, bx * 128, hhi, hlo, 1024, 512, wuqh, wuql, 512,
                  b_uq, 0, 512, 512, qhi, qlo, 0, 0, 3, dsm);
    } else {
        // kr mini-GEMM: 64x64 tile, K=1024, fp32
        float* As = (float*)dsm;
        float* Bs = As + 16 * 64;
        const int tid = threadIdx.x;
        const int brow = (id - 1792) * 64;
        const int tr = (tid >> 4) * 8, tc = (tid & 15) * 4;
        float acc[8][4];
#pragma unroll
        for (int i = 0; i < 8; i++)
#pragma unroll
            for (int j = 0; j < 4; j++) acc[i][j] = 0.f;
        for (int k0 = 0; k0 < 1024; k0 += 16) {
            __syncthreads();
#pragma unroll
            for (int it = 0; it < 8; it++) {
                int i = tid + it * 128;
                int m = i >> 4, kk = i & 15;
                As[kk * 64 + m] = h[(size_t)(brow + m) * 1024 + k0 + kk];
            }
#pragma unroll
            for (int it = 0; it < 8; it++) {
                int i = tid + it * 128;
                int kk = i >> 6, n = i & 63;
                Bs[kk * 64 + n] = W_kr[(size_t)(k0 + kk) * 64 + n];
            }
            __syncthreads();
#pragma unroll
            for (int kk = 0; kk < 16; kk++) {
                float a[8], b[4];
#pragma unroll
                for (int i = 0; i < 8; i++) a[i] = As[kk * 64 + tr + i];
#pragma unroll
                for (int j = 0; j < 4; j++) b[j] = Bs[kk * 64 + tc + j];
#pragma unroll
                for (int i = 0; i < 8; i++)
#pragma unroll
                    for (int j = 0; j < 4; j++) acc[i][j] = fmaf(a[i], b[j], acc[i][j]);
            }
        }
#pragma unroll
        for (int i = 0; i < 8; i++)
#pragma unroll
            for (int j = 0; j < 4; j++)
                kr[(size_t)(brow + tr + i) * 64 + tc + j] = acc[i][j] + b_kr[tc + j];
    }
}

// ---------------------------------------------------------------------------
// Tensor-core flash attention — PERSISTENT with static snake schedule.
// ---------------------------------------------------------------------------
#define QSTR 200
#define KSTR 200
#define VSTR 136
#define Q_ELEMS (128 * QSTR)
#define KST_ELEMS (64 * KSTR)
#define VST_ELEMS (64 * VSTR)
#define K_BASE Q_ELEMS
#define V_BASE (Q_ELEMS + 4 * KST_ELEMS)
#define ATTN_SMEM ((Q_ELEMS + 4 * KST_ELEMS + 4 * VST_ELEMS) * 2)
#define NSM 148

__global__ __launch_bounds__(256, 1)
void attn_tc(const bf16* __restrict__ qhi, const bf16* __restrict__ qlo,
             const bf16* __restrict__ khi, const bf16* __restrict__ klo,
             const bf16* __restrict__ vhi, const bf16* __restrict__ vlo,
             bf16* __restrict__ ohi, bf16* __restrict__ olo)
{
    extern __shared__ bf16 smA[];
    const uint32_t sQh = smem_u32(smA);
    const uint32_t sK  = sQh + K_BASE * 2;
    const uint32_t sV  = sQh + V_BASE * 2;

    const int tid = threadIdx.x, lane = tid & 31, wp = tid >> 5;
    const int c = blockIdx.x;
    const int l16 = lane & 15, lhi = (lane >> 4) * 8;

    for (int p = 0; ; p++) {
        int r = (p & 1) ? ((p + 1) * NSM - 1 - c) : (p * NSM + c);
        if (r >= 512) break;
        const int qi = 15 - (r >> 5);
        const int bh = r & 31;
        const int b = bh >> 4, h = bh & 15;
        const size_t base = (size_t)bh * TT;

        for (int i = tid; i < 128 * 24; i += 256) {
            int rr = i / 24, cc = (i % 24) * 8;
            size_t g = (base + (size_t)qi * 128 + rr) * 192 + cc;
            uint32_t d = (uint32_t)(rr * QSTR + cc) * 2;
            cp16(sQh + d, qhi + g);
            cp16(sK + d, qlo + g);
        }
        cp_commit();
        cp_wait<0>();
        __syncthreads();

        uint32_t qlof[12][4];
#pragma unroll
        for (int kk = 0; kk < 12; kk++) {
            uint32_t aaddr = (uint32_t)((wp * 16 + l16) * QSTR + kk * 16 + lhi) * 2;
            ldm_x4(qlof[kk], sK + aaddr);
        }
        __syncthreads();

        auto issueKV = [&](int st, int kt) {
            uint32_t kb = sK + (uint32_t)(st * 2 * KST_ELEMS) * 2;
            uint32_t vb = sV + (uint32_t)(st * 2 * VST_ELEMS) * 2;
            for (int i = tid; i < 64 * 24; i += 256) {
                int rr = i / 24, cc = (i % 24) * 8;
                size_t g = (base + (size_t)kt * 64 + rr) * 192 + cc;
                uint32_t d = (uint32_t)(rr * KSTR + cc) * 2;
                cp16(kb + d, khi + g);
                cp16(kb + (uint32_t)KST_ELEMS * 2 + d, klo + g);
            }
            for (int i = tid; i < 64 * 16; i += 256) {
                int rr = i / 16, cc = (i % 16) * 8;
                size_t g = (base + (size_t)kt * 64 + rr) * 128 + cc;
                uint32_t d = (uint32_t)(rr * VSTR + cc) * 2;
                cp16(vb + d, vhi + g);
                cp16(vb + (uint32_t)VST_ELEMS * 2 + d, vlo + g);
            }
            cp_commit();
        };

        float o[16][4];
#pragma unroll
        for (int i = 0; i < 16; i++)
#pragma unroll
            for (int f = 0; f < 4; f++) o[i][f] = 0.f;

        float m1 = -1e30f, m2 = -1e30f, l1 = 0.f, l2 = 0.f;
        const int qrow1 = qi * 128 + wp * 16 + (lane >> 2);
        const int qrow2 = qrow1 + 8;
        const int brofs = (lane & 7) + ((lane >> 4) & 1) * 8;
        const int bcofs = ((lane >> 3) & 1) * 8;

        const int nkt = 2 * qi + 2;
        issueKV(0, 0);

        for (int kt = 0; kt < nkt; kt++) {
            if (kt + 1 < nkt) {
                issueKV((kt + 1) & 1, kt + 1);
                cp_wait<1>();
            } else {
                cp_wait<0>();
            }
            __syncthreads();

            const int st = kt & 1;
            const uint32_t sKh = sK + (uint32_t)(st * 2 * KST_ELEMS) * 2;
            const uint32_t sKl = sKh + (uint32_t)KST_ELEMS * 2;
            const uint32_t sVh = sV + (uint32_t)(st * 2 * VST_ELEMS) * 2;
            const uint32_t sVl = sVh + (uint32_t)VST_ELEMS * 2;

            float s[8][4];
#pragma unroll
            for (int j = 0; j < 8; j++)
#pragma unroll
                for (int f = 0; f < 4; f++) s[j][f] = 0.f;

#pragma unroll
            for (int kk = 0; kk < 12; kk++) {
                uint32_t ah[4];
                uint32_t aaddr = (uint32_t)((wp * 16 + l16) * QSTR + kk * 16 + lhi) * 2;
                ldm_x4(ah, sQh + aaddr);
                const uint32_t* al = qlof[kk];
#pragma unroll
                for (int j2 = 0; j2 < 4; j2++) {
                    uint32_t baddr = (uint32_t)((j2 * 16 + brofs) * KSTR + kk * 16 + bcofs) * 2;
                    uint32_t tbv[4], tl[4];
                    ldm_x4(tbv, sKh + baddr);
                    ldm_x4(tl, sKl + baddr);
                    mma_bf16(s[2 * j2],     ah, tbv);
                    mma_bf16(s[2 * j2 + 1], ah, tbv + 2);
                    mma_bf16(s[2 * j2],     ah, tl);
                    mma_bf16(s[2 * j2 + 1], ah, tl + 2);
                    mma_bf16(s[2 * j2],     al, tbv);
                    mma_bf16(s[2 * j2 + 1], al, tbv + 2);
                }
            }

#pragma unroll
            for (int j = 0; j < 8; j++) {
                int k0 = kt * 64 + j * 8 + 2 * (lane & 3);
                if (k0     > qrow1) s[j][0] = -1e30f;
                if (k0 + 1 > qrow1) s[j][1] = -1e30f;
                if (k0     > qrow2) s[j][2] = -1e30f;
                if (k0 + 1 > qrow2) s[j][3] = -1e30f;
            }
            float mr1 = -1e30f, mr2 = -1e30f;
#pragma unroll
            for (int j = 0; j < 8; j++) {
                mr1 = fmaxf(mr1, fmaxf(s[j][0], s[j][1]));
                mr2 = fmaxf(mr2, fmaxf(s[j][2], s[j][3]));
            }
            mr1 = fmaxf(mr1, __shfl_xor_sync(0xffffffffu, mr1, 1));
            mr1 = fmaxf(mr1, __shfl_xor_sync(0xffffffffu, mr1, 2));
            mr2 = fmaxf(mr2, __shfl_xor_sync(0xffffffffu, mr2, 1));
            mr2 = fmaxf(mr2, __shfl_xor_sync(0xffffffffu, mr2, 2));
            float mn1 = fmaxf(m1, mr1), mn2 = fmaxf(m2, mr2);
            float a1 = ex2f(m1 - mn1), a2 = ex2f(m2 - mn2);
            m1 = mn1; m2 = mn2;

            uint32_t phx[8][2], plx[8][2];
            float rs1 = 0.f, rs2 = 0.f;
#pragma unroll
            for (int j = 0; j < 8; j++) {
                float p0 = ex2f(s[j][0] - mn1), p1 = ex2f(s[j][1] - mn1);
                float p2 = ex2f(s[j][2] - mn2), p3 = ex2f(s[j][3] - mn2);
                rs1 += p0 + p1; rs2 += p2 + p3;
                phx[j][0] = packbf2(p0, p1);
                phx[j][1] = packbf2(p2, p3);
                float q0 = p0 - bfround(p0);
                float q1 = p1 - bfround(p1);
                float q2 = p2 - bfround(p2);
                float q3 = p3 - bfround(p3);
                plx[j][0] = packbf2(q0, q1);
                plx[j][1] = packbf2(q2, q3);
            }
            rs1 += __shfl_xor_sync(0xffffffffu, rs1, 1);
            rs1 += __shfl_xor_sync(0xffffffffu, rs1, 2);
            rs2 += __shfl_xor_sync(0xffffffffu, rs2, 1);
            rs2 += __shfl_xor_sync(0xffffffffu, rs2, 2);
            l1 = l1 * a1 + rs1;
            l2 = l2 * a2 + rs2;
#pragma unroll
            for (int t16 = 0; t16 < 16; t16++) {
                o[t16][0] *= a1; o[t16][1] *= a1;
                o[t16][2] *= a2; o[t16][3] *= a2;
            }

#pragma unroll
            for (int kt2 = 0; kt2 < 4; kt2++) {
                uint32_t pa_h[4] = {phx[2 * kt2][0], phx[2 * kt2][1],
                                    phx[2 * kt2 + 1][0], phx[2 * kt2 + 1][1]};
                uint32_t pa_l[4] = {plx[2 * kt2][0], plx[2 * kt2][1],
                                    plx[2 * kt2 + 1][0], plx[2 * kt2 + 1][1]};
                uint32_t vrow = (uint32_t)((kt2 * 16 + l16) * VSTR) * 2;
#pragma unroll
                for (int j2 = 0; j2 < 8; j2++) {
                    uint32_t vaddr = vrow + (uint32_t)(j2 * 16 + lhi) * 2;
                    uint32_t tv[4], tw[4];
                    ldm_x4t(tv, sVh + vaddr);
                    ldm_x4t(tw, sVl + vaddr);
                    mma_bf16(o[2 * j2],     pa_h, tv);
                    mma_bf16(o[2 * j2 + 1], pa_h, tv + 2);
                    mma_bf16(o[2 * j2],     pa_h, tw);
                    mma_bf16(o[2 * j2 + 1], pa_h, tw + 2);
                    mma_bf16(o[2 * j2],     pa_l, tv);
                    mma_bf16(o[2 * j2 + 1], pa_l, tv + 2);
                }
            }
            __syncthreads();
        }

        float inv1 = 1.f / l1, inv2 = 1.f / l2;
        size_t row1 = (size_t)(b * TT + qrow1) * 2048 + h * 128;
        size_t row2 = (size_t)(b * TT + qrow2) * 2048 + h * 128;
#pragma unroll
        for (int t16 = 0; t16 < 16; t16++) {
            int col = t16 * 8 + 2 * (lane & 3);
            float v0 = o[t16][0] * inv1, v1 = o[t16][1] * inv1;
            float v2 = o[t16][2] * inv2, v3 = o[t16][3] * inv2;
            float f0 = bfround(v0), f1 = bfround(v1);
            float f2 = bfround(v2), f3 = bfround(v3);
            *(uint32_t*)&ohi[row1 + col] = packbf2(f0, f1);
            *(uint32_t*)&olo[row1 + col] = packbf2(v0 - f0, v1 - f1);
            *(uint32_t*)&ohi[row2 + col] = packbf2(f2, f3);
            *(uint32_t*)&olo[row2 + col] = packbf2(v2 - f2, v3 - f3);
        }
        __syncthreads();
    }
}

// ---------------------------------------------------------------------------
// Host launcher
// ---------------------------------------------------------------------------
extern "C" void kernel_launch(void* const* d_in, const int* in_sizes, int n_in,
                              void* d_out, int out_size)
{
    (void)in_sizes; (void)n_in; (void)out_size;

    const float* x     = (const float*)d_in[0];
    const float* W_dkv = (const float*)d_in[1];
    const float* b_dkv = (const float*)d_in[2];
    const float* W_kr  = (const float*)d_in[3];
    const float* b_kr  = (const float*)d_in[4];
    const float* W_qr  = (const float*)d_in[5];
    const float* b_qr  = (const float*)d_in[6];
    const float* W_uv  = (const float*)d_in[7];
    const float* b_uv  = (const float*)d_in[8];
    const float* W_uq  = (const float*)d_in[9];
    const float* b_uq  = (const float*)d_in[10];
    const float* W_o   = (const float*)d_in[11];
    const float* b_o   = (const float*)d_in[12];
    float* out = (float*)d_out;

    float *h, *kr, *qr;
    bf16 *xhi, *xlo, *hhi, *hlo, *athi, *atlo;
    bf16 *wdkvh, *wdkvl, *wqrh, *wqrl, *wuvh, *wuvl, *wuqh, *wuql, *woh, *wol;
    bf16 *qhi, *qlo, *khi, *klo, *vhi, *vlo;
    cudaGetSymbolAddress((void**)&h,    g_h);
    cudaGetSymbolAddress((void**)&kr,   g_kr);
    cudaGetSymbolAddress((void**)&qr,   g_qr);
    cudaGetSymbolAddress((void**)&xhi,  g_xhi);
    cudaGetSymbolAddress((void**)&xlo,  g_xlo);
    cudaGetSymbolAddress((void**)&hhi,  g_hhi);
    cudaGetSymbolAddress((void**)&hlo,  g_hlo);
    cudaGetSymbolAddress((void**)&athi, g_athi);
    cudaGetSymbolAddress((void**)&atlo, g_atlo);
    cudaGetSymbolAddress((void**)&wdkvh, g_wdkvh);
    cudaGetSymbolAddress((void**)&wdkvl, g_wdkvl);
    cudaGetSymbolAddress((void**)&wqrh, g_wqrh);
    cudaGetSymbolAddress((void**)&wqrl, g_wqrl);
    cudaGetSymbolAddress((void**)&wuvh, g_wuvh);
    cudaGetSymbolAddress((void**)&wuvl, g_wuvl);
    cudaGetSymbolAddress((void**)&wuqh, g_wuqh);
    cudaGetSymbolAddress((void**)&wuql, g_wuql);
    cudaGetSymbolAddress((void**)&woh,  g_woh);
    cudaGetSymbolAddress((void**)&wol,  g_wol);
    cudaGetSymbolAddress((void**)&qhi, g_qhi);
    cudaGetSymbolAddress((void**)&qlo, g_qlo);
    cudaGetSymbolAddress((void**)&khi, g_khi);
    cudaGetSymbolAddress((void**)&klo, g_klo);
    cudaGetSymbolAddress((void**)&vhi, g_vhi);
    cudaGetSymbolAddress((void**)&vlo, g_vlo);

    cudaFuncSetAttribute(gemm_mma, cudaFuncAttributeMaxDynamicSharedMemorySize, GSMEM);
    cudaFuncSetAttribute(gemm_h_fused, cudaFuncAttributeMaxDynamicSharedMemorySize, GSMEM);
    cudaFuncSetAttribute(gemm_fused3, cudaFuncAttributeMaxDynamicSharedMemorySize, GSMEM);
    cudaFuncSetAttribute(attn_tc, cudaFuncAttributeMaxDynamicSharedMemorySize, ATTN_SMEM);

    // 1) prep_a: x split + W_dkv transpose (h-GEMM inputs only)
    prep_a<<<10240, 256>>>(x, W_dkv, xhi, xlo, wdkvh, wdkvl);
    // 2) h-GEMM + overlapped conversions of W_o/W_qr/W_uv/W_uq
    gemm_h_fused<<<320, 128, GSMEM>>>(xhi, xlo, wdkvh, wdkvl, b_dkv, h, hhi, hlo,
                                      W_o, W_qr, W_uv, W_uq,
                                      woh, wol, wqrh, wqrl,
                                      wuvh, wuvl, wuqh, wuql);
    // 3) fused qr + kv + q GEMMs + kr (one launch, 1856 CTAs)
    gemm_fused3<<<1856, 128, GSMEM>>>(hhi, hlo,
                                      wqrh, wqrl, b_qr, qr,
                                      wuvh, wuvl, b_uv, khi, klo, vhi, vlo,
                                      wuqh, wuql, b_uq, qhi, qlo,
                                      h, W_kr, b_kr, kr);
    // 4) fused rope+split (qr blocks then kr blocks)
    rope_split_both<<<8192 + 512, 256>>>(qr, kr, qhi, qlo, khi, klo);
    // 5) attention (persistent, 148 CTAs, snake schedule)
    attn_tc<<<NSM, 256, ATTN_SMEM>>>(qhi, qlo, khi, klo, vhi, vlo, athi, atlo);
    // 6) out = attn @ W_o + b_o (mode 0)
    gemm_mma<<<dim3(16, 32), 128, GSMEM>>>(athi, atlo, 2048, 0, woh, wol, 2048,
                                           b_o, out, 2048, 2048, 0, 0, 0, 0, 0);
}

// round 17
// speedup vs baseline: 1.1180x; 1.1180x over previous
#include <cuda_runtime.h>
#include <cuda_bf16.h>
#include <math.h>
#include <stdint.h>

// Problem constants
#define BB   2
#define TT   2048
#define CC   2048
#define NHH  16
#define DKK  128
#define LATT 512
#define DHRR 64
#define MROWS (BB * TT)   // 4096

typedef __nv_bfloat16 bf16;

// ---------------------------------------------------------------------------
// Scratch (static device globals -- no allocation allowed)
// ---------------------------------------------------------------------------
__device__ float g_h   [(size_t)MROWS * 1024];
__device__ float g_kr  [(size_t)MROWS * 64];
__device__ float g_qr  [(size_t)MROWS * 1024];

__device__ bf16 g_xhi [(size_t)MROWS * 2048];
__device__ bf16 g_xlo [(size_t)MROWS * 2048];
__device__ bf16 g_hhi [(size_t)MROWS * 1024];
__device__ bf16 g_hlo [(size_t)MROWS * 1024];
__device__ bf16 g_athi[(size_t)MROWS * 2048];
__device__ bf16 g_atlo[(size_t)MROWS * 2048];

__device__ bf16 g_wdkvh[(size_t)1024 * 2048];
__device__ bf16 g_wdkvl[(size_t)1024 * 2048];
__device__ bf16 g_wqrh [(size_t)1024 * 1024];
__device__ bf16 g_wqrl [(size_t)1024 * 1024];
__device__ bf16 g_wuvh [(size_t)4096 * 512];
__device__ bf16 g_wuvl [(size_t)4096 * 512];
__device__ bf16 g_wuqh [(size_t)2048 * 512];
__device__ bf16 g_wuql [(size_t)2048 * 512];
__device__ bf16 g_woh  [(size_t)2048 * 2048];
__device__ bf16 g_wol  [(size_t)2048 * 2048];

__device__ bf16 g_qhi[(size_t)BB * NHH * TT * 192];
__device__ bf16 g_qlo[(size_t)BB * NHH * TT * 192];
__device__ bf16 g_khi[(size_t)BB * NHH * TT * 192];
__device__ bf16 g_klo[(size_t)BB * NHH * TT * 192];
__device__ bf16 g_vhi[(size_t)BB * NHH * TT * 128];
__device__ bf16 g_vlo[(size_t)BB * NHH * TT * 128];

#define SCLQ 0.12754984837627695f   // 1/sqrt(128) * log2(e)

// ---------------------------------------------------------------------------
// PTX helpers
// ---------------------------------------------------------------------------
__device__ __forceinline__ uint32_t smem_u32(const void* p)
{ return (uint32_t)__cvta_generic_to_shared(p); }

__device__ __forceinline__ void cp16(uint32_t dst, const void* src)
{ asm volatile("cp.async.cg.shared.global [%0], [%1], 16;\n" :: "r"(dst), "l"(src)); }

__device__ __forceinline__ void cp_commit()
{ asm volatile("cp.async.commit_group;\n"); }

template <int N>
__device__ __forceinline__ void cp_wait()
{ asm volatile("cp.async.wait_group %0;\n" :: "n"(N)); }

__device__ __forceinline__ void ldm_x4(uint32_t* r, uint32_t addr)
{
    asm volatile("ldmatrix.sync.aligned.m8n8.x4.shared.b16 {%0,%1,%2,%3}, [%4];\n"
        : "=r"(r[0]), "=r"(r[1]), "=r"(r[2]), "=r"(r[3]) : "r"(addr));
}
__device__ __forceinline__ void ldm_x4t(uint32_t* r, uint32_t addr)
{
    asm volatile("ldmatrix.sync.aligned.m8n8.x4.trans.shared.b16 {%0,%1,%2,%3}, [%4];\n"
        : "=r"(r[0]), "=r"(r[1]), "=r"(r[2]), "=r"(r[3]) : "r"(addr));
}
__device__ __forceinline__ void mma_bf16(float* d, const uint32_t* a, const uint32_t* b)
{
    asm volatile(
        "mma.sync.aligned.m16n8k16.row.col.f32.bf16.bf16.f32 "
        "{%0,%1,%2,%3}, {%4,%5,%6,%7}, {%8,%9}, {%0,%1,%2,%3};\n"
        : "+f"(d[0]), "+f"(d[1]), "+f"(d[2]), "+f"(d[3])
        : "r"(a[0]), "r"(a[1]), "r"(a[2]), "r"(a[3]), "r"(b[0]), "r"(b[1]));
}
__device__ __forceinline__ float ex2f(float x)
{ float y; asm("ex2.approx.f32 %0, %1;" : "=f"(y) : "f"(x)); return y; }

__device__ __forceinline__ uint32_t packbf2(float lo, float hi)
{ uint32_t d; asm("cvt.rn.bf16x2.f32 %0, %1, %2;" : "=r"(d) : "f"(hi), "f"(lo)); return d; }

__device__ __forceinline__ float bfround(float v)
{ return __bfloat162float(__float2bfloat16(v)); }

// ---------------------------------------------------------------------------
// prep_all: one launch = split_act(x) + 5 weight transpose/splits.
// ---------------------------------------------------------------------------
__global__ __launch_bounds__(256)
void prep_all(const float* __restrict__ x,
              const float* __restrict__ Wdkv, const float* __restrict__ Wo,
              const float* __restrict__ Wqr,  const float* __restrict__ Wuv,
              const float* __restrict__ Wuq,
              bf16* __restrict__ xhi, bf16* __restrict__ xlo,
              bf16* __restrict__ wdkvh, bf16* __restrict__ wdkvl,
              bf16* __restrict__ woh,  bf16* __restrict__ wol,
              bf16* __restrict__ wqrh, bf16* __restrict__ wqrl,
              bf16* __restrict__ wuvh, bf16* __restrict__ wuvl,
              bf16* __restrict__ wuqh, bf16* __restrict__ wuql)
{
    __shared__ float ts[32][33];
    const int bid = blockIdx.x, tid = threadIdx.x;

    if (bid < 8192) {
        int idx = bid * 256 + tid;
        int m = idx >> 9, k4 = (idx & 511) * 4;
        float4 v = *(const float4*)&x[(size_t)m * 2048 + k4];
        float h0 = bfround(v.x), h1 = bfround(v.y);
        float h2 = bfround(v.z), h3 = bfround(v.w);
        uint2 ph, pl;
        ph.x = packbf2(h0, h1); ph.y = packbf2(h2, h3);
        pl.x = packbf2(v.x - h0, v.y - h1); pl.y = packbf2(v.z - h2, v.w - h3);
        *(uint2*)&xhi[(size_t)m * 2048 + k4] = ph;
        *(uint2*)&xlo[(size_t)m * 2048 + k4] = pl;
        return;
    }

    const float* W; bf16 *hiT, *loT; int K, N, tl;
    if (bid < 10240)      { W = Wdkv; hiT = wdkvh; loT = wdkvl; K = 2048; N = 1024; tl = bid - 8192; }
    else if (bid < 14336) { W = Wo;   hiT = woh;   loT = wol;   K = 2048; N = 2048; tl = bid - 10240; }
    else if (bid < 15360) { W = Wqr;  hiT = wqrh;  loT = wqrl;  K = 1024; N = 1024; tl = bid - 14336; }
    else if (bid < 17408) { W = Wuv;  hiT = wuvh;  loT = wuvl;  K = 512;  N = 4096; tl = bid - 15360; }
    else                  { W = Wuq;  hiT = wuqh;  loT = wuql;  K = 512;  N = 2048; tl = bid - 17408; }

    int ntx = N / 32;
    int n0 = (tl % ntx) * 32, k0 = (tl / ntx) * 32;
    int tx = tid & 31, ty = tid >> 5;
#pragma unroll
    for (int r = 0; r < 4; r++)
        ts[ty + 8 * r][tx] = W[(size_t)(k0 + ty + 8 * r) * N + n0 + tx];
    __syncthreads();
#pragma unroll
    for (int r = 0; r < 4; r++) {
        float v = ts[tx][ty + 8 * r];
        bf16 h = __float2bfloat16(v);
        size_t o = (size_t)(n0 + ty + 8 * r) * K + k0 + tx;
        hiT[o] = h;
        loT[o] = __float2bfloat16(v - __bfloat162float(h));
    }
}

// ---------------------------------------------------------------------------
// Fused rope + hi/lo split + per-head scatter (qr blocks then kr blocks)
// ---------------------------------------------------------------------------
__global__ void rope_split_both(const float* __restrict__ qr,
                                const float* __restrict__ kr,
                                bf16* __restrict__ qhi, bf16* __restrict__ qlo,
                                bf16* __restrict__ khi, bf16* __restrict__ klo)
{
    const int bid = blockIdx.x, tid = threadIdx.x;
    if (bid < 8192) {
        int idx = bid * 256 + tid;
        int row = idx >> 9, i = idx & 511;
        int t = row & 2047, b = row >> 11;
        float theta = (float)exp(-2.0 * (double)i / 1024.0 * log(10000.0));
        float angle = (float)(t + 1) * theta;
        double a = (double)angle;
        float cs = (float)cos(a), sn = (float)sin(a);
        const float* p = qr + (size_t)row * 1024 + 2 * i;
        float x0 = p[0], x1 = p[1];
        float p0 = (x0 * cs - x1 * sn) * SCLQ;
        float p1 = (x1 * cs + x0 * sn) * SCLQ;
        int h = (2 * i) >> 6, d = (2 * i) & 63;
        size_t base = ((size_t)((b * NHH + h) * TT) + t) * 192 + 128 + d;
        float f0 = bfround(p0), f1 = bfround(p1);
        *(uint32_t*)&qhi[base] = packbf2(f0, f1);
        *(uint32_t*)&qlo[base] = packbf2(p0 - f0, p1 - f1);
    } else {
        int idx = (bid - 8192) * 256 + tid;
        int row = idx >> 5, i = idx & 31;
        int t = row & 2047, b = row >> 11;
        float theta = (float)exp(-2.0 * (double)i / 64.0 * log(10000.0));
        float angle = (float)(t + 1) * theta;
        double a = (double)angle;
        float cs = (float)cos(a), sn = (float)sin(a);
        const float* p = kr + (size_t)row * 64 + 2 * i;
        float x0 = p[0], x1 = p[1];
        float p0 = x0 * cs - x1 * sn;
        float p1 = x1 * cs + x0 * sn;
        float f0 = bfround(p0), f1 = bfround(p1);
        uint32_t ph = packbf2(f0, f1), pl = packbf2(p0 - f0, p1 - f1);
#pragma unroll
        for (int hh = 0; hh < NHH; hh++) {
            size_t base = ((size_t)((b * NHH + hh) * TT) + t) * 192 + 128 + 2 * i;
            *(uint32_t*)&khi[base] = ph;
            *(uint32_t*)&klo[base] = pl;
        }
    }
}

// ---------------------------------------------------------------------------
// Shared HMMA GEMM body (compensated hi/lo, fused epilogues) — R12 proven.
// ---------------------------------------------------------------------------
#define TST 40
#define A_ELE (128 * TST)
#define B_ELE (128 * TST)
#define STG_ELE (2 * A_ELE + 2 * B_ELE)
#define GSMEM (2 * STG_ELE * 2)

__device__ __forceinline__
void gemm_body(int brow, int bcol,
               const bf16* __restrict__ Ahi, const bf16* __restrict__ Alo,
               int lda, int aoff,
               const bf16* __restrict__ Bhi, const bf16* __restrict__ Blo,
               int ldb,
               const float* __restrict__ bias,
               float* __restrict__ Y, int ldy, int K,
               bf16* __restrict__ ho, bf16* __restrict__ lo_,
               bf16* __restrict__ ho2, bf16* __restrict__ lo2, int mode,
               bf16* dsm)
{
    const uint32_t sb0 = smem_u32(dsm);
    const int tid = threadIdx.x, lane = tid & 31, wid = tid >> 5;
    const int wm = (wid >> 1) * 64, wn = (wid & 1) * 64;

    auto issue = [&](int st, int kt) {
        uint32_t s = sb0 + (uint32_t)(st * STG_ELE) * 2;
        int ke = kt * 32;
#pragma unroll
        for (int i = 0; i < 4; i++) {
            int c = tid + i * 128;
            int r = c >> 2, sg = (c & 3) * 8;
            uint32_t d = (uint32_t)(r * TST + sg) * 2;
            cp16(s + d, Ahi + (size_t)(brow + r) * lda + aoff + ke + sg);
            cp16(s + (uint32_t)A_ELE * 2 + d,
                 Alo + (size_t)(brow + r) * lda + aoff + ke + sg);
            cp16(s + (uint32_t)(2 * A_ELE) * 2 + d,
                 Bhi + (size_t)(bcol + r) * ldb + ke + sg);
            cp16(s + (uint32_t)(2 * A_ELE + B_ELE) * 2 + d,
                 Blo + (size_t)(bcol + r) * ldb + ke + sg);
        }
        cp_commit();
    };

    float acc[4][8][4];
#pragma unroll
    for (int i = 0; i < 4; i++)
#pragma unroll
        for (int j = 0; j < 8; j++)
#pragma unroll
            for (int f = 0; f < 4; f++) acc[i][j][f] = 0.f;

    const int ntiles = K / 32;
    issue(0, 0);
    issue(1, 1);

    const int l16 = lane & 15, lhi = (lane >> 4) * 8;
    const int brofs = (lane & 7) + ((lane >> 4) & 1) * 8;
    const int bcofs = ((lane >> 3) & 1) * 8;

    for (int kt = 0; kt < ntiles; kt++) {
        if (kt + 1 < ntiles) { cp_wait<1>(); } else { cp_wait<0>(); }
        __syncthreads();
        int cur = kt & 1;
        uint32_t s = sb0 + (uint32_t)(cur * STG_ELE) * 2;
        uint32_t sAh = s, sAl = s + (uint32_t)A_ELE * 2;
        uint32_t sBh = s + (uint32_t)(2 * A_ELE) * 2;
        uint32_t sBl = sBh + (uint32_t)B_ELE * 2;

#pragma unroll
        for (int kk = 0; kk < 32; kk += 16) {
            uint32_t bh[4][4], bl[4][4];
#pragma unroll
            for (int j2 = 0; j2 < 4; j2++) {
                uint32_t baddr =
                    (uint32_t)((wn + j2 * 16 + brofs) * TST + kk + bcofs) * 2;
                ldm_x4(bh[j2], sBh + baddr);
                ldm_x4(bl[j2], sBl + baddr);
            }
#pragma unroll
            for (int i = 0; i < 4; i++) {
                uint32_t ah[4], al[4];
                uint32_t aaddr = (uint32_t)((wm + i * 16 + l16) * TST + kk + lhi) * 2;
                ldm_x4(ah, sAh + aaddr);
                ldm_x4(al, sAl + aaddr);
#pragma unroll
                for (int j2 = 0; j2 < 4; j2++) {
                    mma_bf16(acc[i][2 * j2],     ah, bh[j2]);
                    mma_bf16(acc[i][2 * j2 + 1], ah, bh[j2] + 2);
                }
#pragma unroll
                for (int j2 = 0; j2 < 4; j2++) {
                    mma_bf16(acc[i][2 * j2],     ah, bl[j2]);
                    mma_bf16(acc[i][2 * j2 + 1], ah, bl[j2] + 2);
                }
#pragma unroll
                for (int j2 = 0; j2 < 4; j2++) {
                    mma_bf16(acc[i][2 * j2],     al, bh[j2]);
                    mma_bf16(acc[i][2 * j2 + 1], al, bh[j2] + 2);
                }
            }
        }
        __syncthreads();
        if (kt + 2 < ntiles) issue(cur, kt + 2);
    }

#pragma unroll
    for (int i = 0; i < 4; i++) {
#pragma unroll
        for (int j = 0; j < 8; j++) {
            int r0 = brow + wm + i * 16 + (lane >> 2);
            int c0 = bcol + wn + j * 8 + (lane & 3) * 2;
            float b0 = bias[c0], b1 = bias[c0 + 1];
            float v00 = acc[i][j][0] + b0, v01 = acc[i][j][1] + b1;
            float v10 = acc[i][j][2] + b0, v11 = acc[i][j][3] + b1;

            if (mode <= 1) {
                *(float2*)&Y[(size_t)r0 * ldy + c0]       = make_float2(v00, v01);
                *(float2*)&Y[(size_t)(r0 + 8) * ldy + c0] = make_float2(v10, v11);
            }
            if (mode == 1) {
                float f00 = bfround(v00), f01 = bfround(v01);
                float f10 = bfround(v10), f11 = bfround(v11);
                *(uint32_t*)&ho [(size_t)r0 * ldy + c0]       = packbf2(f00, f01);
                *(uint32_t*)&lo_[(size_t)r0 * ldy + c0]       = packbf2(v00 - f00, v01 - f01);
                *(uint32_t*)&ho [(size_t)(r0 + 8) * ldy + c0] = packbf2(f10, f11);
                *(uint32_t*)&lo_[(size_t)(r0 + 8) * ldy + c0] = packbf2(v10 - f10, v11 - f11);
            } else if (mode == 2) {
#pragma unroll
                for (int rr = 0; rr < 2; rr++) {
                    int r = r0 + rr * 8;
                    float va = rr ? v10 : v00, vb = rr ? v11 : v01;
                    int b = r >> 11, t = r & 2047;
                    float fa = bfround(va), fb = bfround(vb);
                    if (c0 < 2048) {
                        int hh = c0 >> 7, d = c0 & 127;
                        size_t base = ((size_t)(b * NHH + hh) * TT + t) * 192 + d;
                        *(uint32_t*)&ho [base] = packbf2(fa, fb);
                        *(uint32_t*)&lo_[base] = packbf2(va - fa, vb - fb);
                    } else {
                        int c2 = c0 - 2048;
                        int hh = c2 >> 7, d = c2 & 127;
                        size_t base = ((size_t)(b * NHH + hh) * TT + t) * 128 + d;
                        *(uint32_t*)&ho2[base] = packbf2(fa, fb);
                        *(uint32_t*)&lo2[base] = packbf2(va - fa, vb - fb);
                    }
                }
            } else if (mode == 3) {
#pragma unroll
                for (int rr = 0; rr < 2; rr++) {
                    int r = r0 + rr * 8;
                    float va = (rr ? v10 : v00) * SCLQ, vb = (rr ? v11 : v01) * SCLQ;
                    int b = r >> 11, t = r & 2047;
                    int hh = c0 >> 7, d = c0 & 127;
                    size_t base = ((size_t)(b * NHH + hh) * TT + t) * 192 + d;
                    float fa = bfround(va), fb = bfround(vb);
                    *(uint32_t*)&ho [base] = packbf2(fa, fb);
                    *(uint32_t*)&lo_[base] = packbf2(va - fa, vb - fb);
                }
            }
        }
    }
}

// Standalone GEMM (h and out projections)
__global__ __launch_bounds__(128, 2)
void gemm_mma(const bf16* __restrict__ Ahi, const bf16* __restrict__ Alo,
              int lda, int aoff,
              const bf16* __restrict__ Bhi, const bf16* __restrict__ Blo,
              int ldb,
              const float* __restrict__ bias,
              float* __restrict__ Y, int ldy, int K,
              bf16* __restrict__ ho, bf16* __restrict__ lo_,
              bf16* __restrict__ ho2, bf16* __restrict__ lo2, int mode)
{
    extern __shared__ bf16 dsm[];
    gemm_body(blockIdx.y * 128, blockIdx.x * 128, Ahi, Alo, lda, aoff,
              Bhi, Blo, ldb, bias, Y, ldy, K, ho, lo_, ho2, lo2, mode, dsm);
}

// Fused kr + qr + kv + q GEMMs; one launch, range dispatch.
// Blocks: [0,128) kr (32-row tiles, LONGEST-per-block -> first);
//         [128,384) qr; [384,1408) kv; [1408,1920) q.
__global__ __launch_bounds__(128, 2)
void gemm_fused3(const bf16* __restrict__ hhi, const bf16* __restrict__ hlo,
                 const bf16* __restrict__ wqrh, const bf16* __restrict__ wqrl,
                 const float* __restrict__ b_qr, float* __restrict__ qr,
                 const bf16* __restrict__ wuvh, const bf16* __restrict__ wuvl,
                 const float* __restrict__ b_uv,
                 bf16* __restrict__ khi, bf16* __restrict__ klo,
                 bf16* __restrict__ vhi, bf16* __restrict__ vlo,
                 const bf16* __restrict__ wuqh, const bf16* __restrict__ wuql,
                 const float* __restrict__ b_uq,
                 bf16* __restrict__ qhi, bf16* __restrict__ qlo,
                 const float* __restrict__ h, const float* __restrict__ W_kr,
                 const float* __restrict__ b_kr, float* __restrict__ kr)
{
    extern __shared__ bf16 dsm[];
    const int id = blockIdx.x;
    if (id < 128) {
        // kr mini-GEMM: 32x64 tile, K=1024, fp32 (k-sequential order preserved)
        float* As = (float*)dsm;             // [16][32]
        float* Bs = As + 16 * 32;            // [16][64]
        const int tid = threadIdx.x;
        const int brow = id * 32;
        const int tr = (tid >> 4) * 4, tc = (tid & 15) * 4;
        float acc[4][4];
#pragma unroll
        for (int i = 0; i < 4; i++)
#pragma unroll
            for (int j = 0; j < 4; j++) acc[i][j] = 0.f;
        for (int k0 = 0; k0 < 1024; k0 += 16) {
            __syncthreads();
#pragma unroll
            for (int it = 0; it < 4; it++) {
                int i = tid + it * 128;
                int m = i >> 4, kk = i & 15;
                As[kk * 32 + m] = h[(size_t)(brow + m) * 1024 + k0 + kk];
            }
#pragma unroll
            for (int it = 0; it < 8; it++) {
                int i = tid + it * 128;
                int kk = i >> 6, n = i & 63;
                Bs[kk * 64 + n] = W_kr[(size_t)(k0 + kk) * 64 + n];
            }
            __syncthreads();
#pragma unroll
            for (int kk = 0; kk < 16; kk++) {
                float a[4], b[4];
#pragma unroll
                for (int i = 0; i < 4; i++) a[i] = As[kk * 32 + tr + i];
#pragma unroll
                for (int j = 0; j < 4; j++) b[j] = Bs[kk * 64 + tc + j];
#pragma unroll
                for (int i = 0; i < 4; i++)
#pragma unroll
                    for (int j = 0; j < 4; j++) acc[i][j] = fmaf(a[i], b[j], acc[i][j]);
            }
        }
#pragma unroll
        for (int i = 0; i < 4; i++)
#pragma unroll
            for (int j = 0; j < 4; j++)
                kr[(size_t)(brow + tr + i) * 64 + tc + j] = acc[i][j] + b_kr[tc + j];
    } else if (id < 384) {
        int t = id - 128;
        int bx = t & 7, by = t >> 3;
        gemm_body(by * 128, bx * 128, hhi, hlo, 1024, 0, wqrh, wqrl, 1024,
                  b_qr, qr, 1024, 1024, 0, 0, 0, 0, 0, dsm);
    } else if (id < 1408) {
        int t = id - 384;
        int bx = t & 31, by = t >> 5;
        gemm_body(by * 128, bx * 128, hhi, hlo, 1024, 0, wuvh, wuvl, 512,
                  b_uv, 0, 512, 512, khi, klo, vhi, vlo, 2, dsm);
    } else {
        int t = id - 1408;
        int bx = t & 15, by = t >> 4;
        gemm_body(by * 128, bx * 128, hhi, hlo, 1024, 512, wuqh, wuql, 512,
                  b_uq, 0, 512, 512, qhi, qlo, 0, 0, 3, dsm);
    }
}

// ---------------------------------------------------------------------------
// Tensor-core flash attention — PERSISTENT with static snake schedule.
// ---------------------------------------------------------------------------
#define QSTR 200
#define KSTR 200
#define VSTR 136
#define Q_ELEMS (128 * QSTR)
#define KST_ELEMS (64 * KSTR)
#define VST_ELEMS (64 * VSTR)
#define K_BASE Q_ELEMS
#define V_BASE (Q_ELEMS + 4 * KST_ELEMS)
#define ATTN_SMEM ((Q_ELEMS + 4 * KST_ELEMS + 4 * VST_ELEMS) * 2)
#define NSM 148

__global__ __launch_bounds__(256, 1)
void attn_tc(const bf16* __restrict__ qhi, const bf16* __restrict__ qlo,
             const bf16* __restrict__ khi, const bf16* __restrict__ klo,
             const bf16* __restrict__ vhi, const bf16* __restrict__ vlo,
             bf16* __restrict__ ohi, bf16* __restrict__ olo)
{
    extern __shared__ bf16 smA[];
    const uint32_t sQh = smem_u32(smA);
    const uint32_t sK  = sQh + K_BASE * 2;
    const uint32_t sV  = sQh + V_BASE * 2;

    const int tid = threadIdx.x, lane = tid & 31, wp = tid >> 5;
    const int c = blockIdx.x;
    const int l16 = lane & 15, lhi = (lane >> 4) * 8;

    for (int p = 0; ; p++) {
        int r = (p & 1) ? ((p + 1) * NSM - 1 - c) : (p * NSM + c);
        if (r >= 512) break;
        const int qi = 15 - (r >> 5);
        const int bh = r & 31;
        const int b = bh >> 4, h = bh & 15;
        const size_t base = (size_t)bh * TT;

        for (int i = tid; i < 128 * 24; i += 256) {
            int rr = i / 24, cc = (i % 24) * 8;
            size_t g = (base + (size_t)qi * 128 + rr) * 192 + cc;
            uint32_t d = (uint32_t)(rr * QSTR + cc) * 2;
            cp16(sQh + d, qhi + g);
            cp16(sK + d, qlo + g);
        }
        cp_commit();
        cp_wait<0>();
        __syncthreads();

        uint32_t qlof[12][4];
#pragma unroll
        for (int kk = 0; kk < 12; kk++) {
            uint32_t aaddr = (uint32_t)((wp * 16 + l16) * QSTR + kk * 16 + lhi) * 2;
            ldm_x4(qlof[kk], sK + aaddr);
        }
        __syncthreads();

        auto issueKV = [&](int st, int kt) {
            uint32_t kb = sK + (uint32_t)(st * 2 * KST_ELEMS) * 2;
            uint32_t vb = sV + (uint32_t)(st * 2 * VST_ELEMS) * 2;
            for (int i = tid; i < 64 * 24; i += 256) {
                int rr = i / 24, cc = (i % 24) * 8;
                size_t g = (base + (size_t)kt * 64 + rr) * 192 + cc;
                uint32_t d = (uint32_t)(rr * KSTR + cc) * 2;
                cp16(kb + d, khi + g);
                cp16(kb + (uint32_t)KST_ELEMS * 2 + d, klo + g);
            }
            for (int i = tid; i < 64 * 16; i += 256) {
                int rr = i / 16, cc = (i % 16) * 8;
                size_t g = (base + (size_t)kt * 64 + rr) * 128 + cc;
                uint32_t d = (uint32_t)(rr * VSTR + cc) * 2;
                cp16(vb + d, vhi + g);
                cp16(vb + (uint32_t)VST_ELEMS * 2 + d, vlo + g);
            }
            cp_commit();
        };

        float o[16][4];
#pragma unroll
        for (int i = 0; i < 16; i++)
#pragma unroll
            for (int f = 0; f < 4; f++) o[i][f] = 0.f;

        float m1 = -1e30f, m2 = -1e30f, l1 = 0.f, l2 = 0.f;
        const int qrow1 = qi * 128 + wp * 16 + (lane >> 2);
        const int qrow2 = qrow1 + 8;
        const int brofs = (lane & 7) + ((lane >> 4) & 1) * 8;
        const int bcofs = ((lane >> 3) & 1) * 8;

        const int nkt = 2 * qi + 2;
        issueKV(0, 0);

        for (int kt = 0; kt < nkt; kt++) {
            if (kt + 1 < nkt) {
                issueKV((kt + 1) & 1, kt + 1);
                cp_wait<1>();
            } else {
                cp_wait<0>();
            }
            __syncthreads();

            const int st = kt & 1;
            const uint32_t sKh = sK + (uint32_t)(st * 2 * KST_ELEMS) * 2;
            const uint32_t sKl = sKh + (uint32_t)KST_ELEMS * 2;
            const uint32_t sVh = sV + (uint32_t)(st * 2 * VST_ELEMS) * 2;
            const uint32_t sVl = sVh + (uint32_t)VST_ELEMS * 2;

            float s[8][4];
#pragma unroll
            for (int j = 0; j < 8; j++)
#pragma unroll
                for (int f = 0; f < 4; f++) s[j][f] = 0.f;

#pragma unroll
            for (int kk = 0; kk < 12; kk++) {
                uint32_t ah[4];
                uint32_t aaddr = (uint32_t)((wp * 16 + l16) * QSTR + kk * 16 + lhi) * 2;
                ldm_x4(ah, sQh + aaddr);
                const uint32_t* al = qlof[kk];
#pragma unroll
                for (int j2 = 0; j2 < 4; j2++) {
                    uint32_t baddr = (uint32_t)((j2 * 16 + brofs) * KSTR + kk * 16 + bcofs) * 2;
                    uint32_t tbv[4], tl[4];
                    ldm_x4(tbv, sKh + baddr);
                    ldm_x4(tl, sKl + baddr);
                    mma_bf16(s[2 * j2],     ah, tbv);
                    mma_bf16(s[2 * j2 + 1], ah, tbv + 2);
                    mma_bf16(s[2 * j2],     ah, tl);
                    mma_bf16(s[2 * j2 + 1], ah, tl + 2);
                    mma_bf16(s[2 * j2],     al, tbv);
                    mma_bf16(s[2 * j2 + 1], al, tbv + 2);
                }
            }

#pragma unroll
            for (int j = 0; j < 8; j++) {
                int k0 = kt * 64 + j * 8 + 2 * (lane & 3);
                if (k0     > qrow1) s[j][0] = -1e30f;
                if (k0 + 1 > qrow1) s[j][1] = -1e30f;
                if (k0     > qrow2) s[j][2] = -1e30f;
                if (k0 + 1 > qrow2) s[j][3] = -1e30f;
            }
            float mr1 = -1e30f, mr2 = -1e30f;
#pragma unroll
            for (int j = 0; j < 8; j++) {
                mr1 = fmaxf(mr1, fmaxf(s[j][0], s[j][1]));
                mr2 = fmaxf(mr2, fmaxf(s[j][2], s[j][3]));
            }
            mr1 = fmaxf(mr1, __shfl_xor_sync(0xffffffffu, mr1, 1));
            mr1 = fmaxf(mr1, __shfl_xor_sync(0xffffffffu, mr1, 2));
            mr2 = fmaxf(mr2, __shfl_xor_sync(0xffffffffu, mr2, 1));
            mr2 = fmaxf(mr2, __shfl_xor_sync(0xffffffffu, mr2, 2));
            float mn1 = fmaxf(m1, mr1), mn2 = fmaxf(m2, mr2);
            float a1 = ex2f(m1 - mn1), a2 = ex2f(m2 - mn2);
            m1 = mn1; m2 = mn2;

            uint32_t phx[8][2], plx[8][2];
            float rs1 = 0.f, rs2 = 0.f;
#pragma unroll
            for (int j = 0; j < 8; j++) {
                float p0 = ex2f(s[j][0] - mn1), p1 = ex2f(s[j][1] - mn1);
                float p2 = ex2f(s[j][2] - mn2), p3 = ex2f(s[j][3] - mn2);
                rs1 += p0 + p1; rs2 += p2 + p3;
                phx[j][0] = packbf2(p0, p1);
                phx[j][1] = packbf2(p2, p3);
                float q0 = p0 - bfround(p0);
                float q1 = p1 - bfround(p1);
                float q2 = p2 - bfround(p2);
                float q3 = p3 - bfround(p3);
                plx[j][0] = packbf2(q0, q1);
                plx[j][1] = packbf2(q2, q3);
            }
            rs1 += __shfl_xor_sync(0xffffffffu, rs1, 1);
            rs1 += __shfl_xor_sync(0xffffffffu, rs1, 2);
            rs2 += __shfl_xor_sync(0xffffffffu, rs2, 1);
            rs2 += __shfl_xor_sync(0xffffffffu, rs2, 2);
            l1 = l1 * a1 + rs1;
            l2 = l2 * a2 + rs2;
#pragma unroll
            for (int t16 = 0; t16 < 16; t16++) {
                o[t16][0] *= a1; o[t16][1] *= a1;
                o[t16][2] *= a2; o[t16][3] *= a2;
            }

#pragma unroll
            for (int kt2 = 0; kt2 < 4; kt2++) {
                uint32_t pa_h[4] = {phx[2 * kt2][0], phx[2 * kt2][1],
                                    phx[2 * kt2 + 1][0], phx[2 * kt2 + 1][1]};
                uint32_t pa_l[4] = {plx[2 * kt2][0], plx[2 * kt2][1],
                                    plx[2 * kt2 + 1][0], plx[2 * kt2 + 1][1]};
                uint32_t vrow = (uint32_t)((kt2 * 16 + l16) * VSTR) * 2;
#pragma unroll
                for (int j2 = 0; j2 < 8; j2++) {
                    uint32_t vaddr = vrow + (uint32_t)(j2 * 16 + lhi) * 2;
                    uint32_t tv[4], tw[4];
                    ldm_x4t(tv, sVh + vaddr);
                    ldm_x4t(tw, sVl + vaddr);
                    mma_bf16(o[2 * j2],     pa_h, tv);
                    mma_bf16(o[2 * j2 + 1], pa_h, tv + 2);
                    mma_bf16(o[2 * j2],     pa_h, tw);
                    mma_bf16(o[2 * j2 + 1], pa_h, tw + 2);
                    mma_bf16(o[2 * j2],     pa_l, tv);
                    mma_bf16(o[2 * j2 + 1], pa_l, tv + 2);
                }
            }
            __syncthreads();
        }

        float inv1 = 1.f / l1, inv2 = 1.f / l2;
        size_t row1 = (size_t)(b * TT + qrow1) * 2048 + h * 128;
        size_t row2 = (size_t)(b * TT + qrow2) * 2048 + h * 128;
#pragma unroll
        for (int t16 = 0; t16 < 16; t16++) {
            int col = t16 * 8 + 2 * (lane & 3);
            float v0 = o[t16][0] * inv1, v1 = o[t16][1] * inv1;
            float v2 = o[t16][2] * inv2, v3 = o[t16][3] * inv2;
            float f0 = bfround(v0), f1 = bfround(v1);
            float f2 = bfround(v2), f3 = bfround(v3);
            *(uint32_t*)&ohi[row1 + col] = packbf2(f0, f1);
            *(uint32_t*)&olo[row1 + col] = packbf2(v0 - f0, v1 - f1);
            *(uint32_t*)&ohi[row2 + col] = packbf2(f2, f3);
            *(uint32_t*)&olo[row2 + col] = packbf2(v2 - f2, v3 - f3);
        }
        __syncthreads();
    }
}

// ---------------------------------------------------------------------------
// Host launcher
// ---------------------------------------------------------------------------
extern "C" void kernel_launch(void* const* d_in, const int* in_sizes, int n_in,
                              void* d_out, int out_size)
{
    (void)in_sizes; (void)n_in; (void)out_size;

    const float* x     = (const float*)d_in[0];
    const float* W_dkv = (const float*)d_in[1];
    const float* b_dkv = (const float*)d_in[2];
    const float* W_kr  = (const float*)d_in[3];
    const float* b_kr  = (const float*)d_in[4];
    const float* W_qr  = (const float*)d_in[5];
    const float* b_qr  = (const float*)d_in[6];
    const float* W_uv  = (const float*)d_in[7];
    const float* b_uv  = (const float*)d_in[8];
    const float* W_uq  = (const float*)d_in[9];
    const float* b_uq  = (const float*)d_in[10];
    const float* W_o   = (const float*)d_in[11];
    const float* b_o   = (const float*)d_in[12];
    float* out = (float*)d_out;

    float *h, *kr, *qr;
    bf16 *xhi, *xlo, *hhi, *hlo, *athi, *atlo;
    bf16 *wdkvh, *wdkvl, *wqrh, *wqrl, *wuvh, *wuvl, *wuqh, *wuql, *woh, *wol;
    bf16 *qhi, *qlo, *khi, *klo, *vhi, *vlo;
    cudaGetSymbolAddress((void**)&h,    g_h);
    cudaGetSymbolAddress((void**)&kr,   g_kr);
    cudaGetSymbolAddress((void**)&qr,   g_qr);
    cudaGetSymbolAddress((void**)&xhi,  g_xhi);
    cudaGetSymbolAddress((void**)&xlo,  g_xlo);
    cudaGetSymbolAddress((void**)&hhi,  g_hhi);
    cudaGetSymbolAddress((void**)&hlo,  g_hlo);
    cudaGetSymbolAddress((void**)&athi, g_athi);
    cudaGetSymbolAddress((void**)&atlo, g_atlo);
    cudaGetSymbolAddress((void**)&wdkvh, g_wdkvh);
    cudaGetSymbolAddress((void**)&wdkvl, g_wdkvl);
    cudaGetSymbolAddress((void**)&wqrh, g_wqrh);
    cudaGetSymbolAddress((void**)&wqrl, g_wqrl);
    cudaGetSymbolAddress((void**)&wuvh, g_wuvh);
    cudaGetSymbolAddress((void**)&wuvl, g_wuvl);
    cudaGetSymbolAddress((void**)&wuqh, g_wuqh);
    cudaGetSymbolAddress((void**)&wuql, g_wuql);
    cudaGetSymbolAddress((void**)&woh,  g_woh);
    cudaGetSymbolAddress((void**)&wol,  g_wol);
    cudaGetSymbolAddress((void**)&qhi, g_qhi);
    cudaGetSymbolAddress((void**)&qlo, g_qlo);
    cudaGetSymbolAddress((void**)&khi, g_khi);
    cudaGetSymbolAddress((void**)&klo, g_klo);
    cudaGetSymbolAddress((void**)&vhi, g_vhi);
    cudaGetSymbolAddress((void**)&vlo, g_vlo);

    cudaFuncSetAttribute(gemm_mma, cudaFuncAttributeMaxDynamicSharedMemorySize, GSMEM);
    cudaFuncSetAttribute(gemm_fused3, cudaFuncAttributeMaxDynamicSharedMemorySize, GSMEM);
    cudaFuncSetAttribute(attn_tc, cudaFuncAttributeMaxDynamicSharedMemorySize, ATTN_SMEM);

    // 1) prep: x split + all 5 weight transpose/splits
    prep_all<<<18432, 256>>>(x, W_dkv, W_o, W_qr, W_uv, W_uq,
                             xhi, xlo, wdkvh, wdkvl, woh, wol,
                             wqrh, wqrl, wuvh, wuvl, wuqh, wuql);
    // 2) h = x @ W_dkv + b_dkv (mode 1: fp32 h + hhi/hlo)
    gemm_mma<<<dim3(8, 32), 128, GSMEM>>>(xhi, xlo, 2048, 0, wdkvh, wdkvl, 2048,
                                          b_dkv, h, 1024, 2048, hhi, hlo, 0, 0, 1);
    // 3) fused kr + qr + kv + q GEMMs (one launch, 1920 CTAs, kr first)
    gemm_fused3<<<1920, 128, GSMEM>>>(hhi, hlo,
                                      wqrh, wqrl, b_qr, qr,
                                      wuvh, wuvl, b_uv, khi, klo, vhi, vlo,
                                      wuqh, wuql, b_uq, qhi, qlo,
                                      h, W_kr, b_kr, kr);
    // 4) fused rope+split (qr blocks then kr blocks)
    rope_split_both<<<8192 + 512, 256>>>(qr, kr, qhi, qlo, khi, klo);
    // 5) attention (persistent, 148 CTAs, snake schedule)
    attn_tc<<<NSM, 256, ATTN_SMEM>>>(qhi, qlo, khi, klo, vhi, vlo, athi, atlo);
    // 6) out = attn @ W_o + b_o (mode 0)
    gemm_mma<<<dim3(16, 32), 128, GSMEM>>>(athi, atlo, 2048, 0, woh, wol, 2048,
                                           b_o, out, 2048, 2048, 0, 0, 0, 0, 0);
}